// round 12
// baseline (speedup 1.0000x reference)
#include <cuda_runtime.h>
#include <cuda_bf16.h>

// Causal depthwise conv1d (K=4) + SiLU over x:(B,S,D) fp32, channel-innermost.
// y[b,s,d] = silu( sum_{k=0..3} w[d,0,k] * x[b, s-3+k, d] )  (zero left-pad)
//
// R10: deepen per-warp MLP. Evidence: R9 (72 regs, 32 warps, MLP=8) beat all
// higher-occupancy variants; R8 (forced 42 regs, 67% occ) was 62% slower.
// Performance tracks per-warp batched loads, not warp count.
//  - CHUNK=32, GROUP=16: 16 LDG.128.CG in flight per warp per batch;
//    halo reads drop to 9.4% (L2-served). Grid 4096.
//  - expected regs ~100-110 -> 4 blocks/SM -> 16 warps x MLP16 = 256
//    outstanding LDG.128 per SM, same as R9 but cheaper issue per byte.
//  - __ldcg bulk loads (no L1 reuse in-block), __fdividef SiLU, __stcs stores.

#define TPB   128
#define CHUNK 32
#define GROUP 16

__device__ __forceinline__ float silu_fast(float v) {
    return __fdividef(v, 1.0f + __expf(-v));
}

__global__ __launch_bounds__(TPB)
void causal_conv1d_silu_kernel(const float4* __restrict__ x,
                               const float4* __restrict__ w,   // (D,1,K) -> per-channel float4 taps
                               float4* __restrict__ y,
                               int S, int D4)
{
    const int d4 = blockIdx.x * TPB + threadIdx.x;   // float4-channel group
    const int s0 = blockIdx.y * CHUNK;
    const int b  = blockIdx.z;

    const float4 w0 = w[4 * d4 + 0];
    const float4 w1 = w[4 * d4 + 1];
    const float4 w2 = w[4 * d4 + 2];
    const float4 w3 = w[4 * d4 + 3];

    const size_t st   = (size_t)D4;
    const size_t base = ((size_t)b * S + s0) * st + (size_t)d4;

    // History: p1 = x[s0-1], p2 = x[s0-2], p3 = x[s0-3] (zero before s=0).
    const float4 z = make_float4(0.f, 0.f, 0.f, 0.f);
    float4 p1 = z, p2 = z, p3 = z;
    if (s0 >= 3) {
        p1 = __ldcg(&x[base - 1 * st]);
        p2 = __ldcg(&x[base - 2 * st]);
        p3 = __ldcg(&x[base - 3 * st]);
    }

    #pragma unroll
    for (int g = 0; g < CHUNK; g += GROUP) {
        // Batched loads: GROUP independent LDG.128.CG in flight before compute.
        float4 c[GROUP];
        #pragma unroll
        for (int j = 0; j < GROUP; ++j)
            c[j] = __ldcg(&x[base + (size_t)(g + j) * st]);

        #pragma unroll
        for (int j = 0; j < GROUP; ++j) {
            const float4 cur = c[j];
            float4 r;
            // taps: k=0 -> x[s-3] (oldest) ... k=3 -> x[s]
            r.x = w0.x * p3.x + w0.y * p2.x + w0.z * p1.x + w0.w * cur.x;
            r.y = w1.x * p3.y + w1.y * p2.y + w1.z * p1.y + w1.w * cur.y;
            r.z = w2.x * p3.z + w2.y * p2.z + w2.z * p1.z + w2.w * cur.z;
            r.w = w3.x * p3.w + w3.y * p2.w + w3.z * p1.w + w3.w * cur.w;

            r.x = silu_fast(r.x);
            r.y = silu_fast(r.y);
            r.z = silu_fast(r.z);
            r.w = silu_fast(r.w);

            __stcs(&y[base + (size_t)(g + j) * st], r);

            p3 = p2; p2 = p1; p1 = cur;
        }
    }
}

extern "C" void kernel_launch(void* const* d_in, const int* in_sizes, int n_in,
                              void* d_out, int out_size)
{
    const float* x = (const float*)d_in[0];
    const float* w = (const float*)d_in[1];
    float*       y = (float*)d_out;

    const int K = 4;
    const int D = in_sizes[1] / K;          // 2048
    const int S = 8192;
    const int B = in_sizes[0] / (S * D);    // 4

    const int D4 = D / 4;                   // 512

    dim3 block(TPB);
    dim3 grid(D4 / TPB, S / CHUNK, B);      // (4, 256, 4) = 4096 blocks

    causal_conv1d_silu_kernel<<<grid, block>>>(
        (const float4*)x, (const float4*)w, (float4*)y, S, D4);
}